// round 2
// baseline (speedup 1.0000x reference)
#include <cuda_runtime.h>
#include <cuda_bf16.h>

// Problem constants (fixed by the reference setup_inputs)
#define B_    4
#define CIN   128
#define COUT  128
#define H_    64
#define W_    64
#define T_    16
#define SS    512

// Tiling
#define CK    8     // cin chunk staged in smem
#define COT   32    // cout per block
#define TH    4     // h tile
#define TW    4     // w tile

// Scratch (no cudaMalloc allowed)
__device__ float g_s[B_ * CIN];        // style modulation scale per (b, cin)
__device__ float g_siginv[B_ * COUT];  // demodulation per (b, cout)

// ---------------------------------------------------------------------------
// Kernel 1: s[b,i] = style[b,:] . style_w[i,:] + style_b[i]
// grid (4), block (128): thread i of block b computes one dot of length 512.
// ---------------------------------------------------------------------------
__global__ void k_style(const float* __restrict__ style,
                        const float* __restrict__ style_w,
                        const float* __restrict__ style_b) {
    int b = blockIdx.x;
    int i = threadIdx.x;
    const float* st = style + (size_t)b * SS;
    const float* sw = style_w + (size_t)i * SS;
    float acc = 0.f;
#pragma unroll 8
    for (int k = 0; k < SS; ++k) acc += st[k] * sw[k];
    g_s[b * CIN + i] = acc + style_b[i];
}

// ---------------------------------------------------------------------------
// Kernel 2: sig_inv[b,o] = rsqrt( sum_i (sum_tap w[o,i,tap]^2) * s[b,i]^2 + 1e-8 )
// grid (4), block (128): thread o of block b.
// ---------------------------------------------------------------------------
__global__ void k_sig(const float* __restrict__ weight) {
    int b = blockIdx.x;
    int o = threadIdx.x;
    const float* wrow = weight + (size_t)o * CIN * 9;
    float acc = 0.f;
    for (int i = 0; i < CIN; ++i) {
        float wsq = 0.f;
#pragma unroll
        for (int tap = 0; tap < 9; ++tap) {
            float w = wrow[i * 9 + tap];
            wsq += w * w;
        }
        float sv = g_s[b * CIN + i];
        acc += wsq * sv * sv;
    }
    g_siginv[b * COUT + o] = rsqrtf(acc + 1e-8f);
}

// ---------------------------------------------------------------------------
// Kernel 3: main modulated conv.
// Output tile per block: 32 couts x (4h x 4w) x 16t.
// Thread mapping (256 threads): tg = t-quad (4 t's), p = spatial pos (16),
// cg = cout octet (4 groups of 8).
// ---------------------------------------------------------------------------
__global__ void __launch_bounds__(256, 2)
k_conv(const float* __restrict__ x,
       const float* __restrict__ weight,
       const float* __restrict__ noise,
       const float* __restrict__ noise_param,
       const float* __restrict__ bias_param,
       float* __restrict__ out) {
    __shared__ float xs[CK][36][T_];      // [ci][(h+2)*(w+2) pos][t], s-scaled
    __shared__ float ws[COT][CK][9];      // [cout][ci][tap]

    const int tid = threadIdx.x;
    const int tg = tid & 3;               // t quad: t = tg*4 .. tg*4+3
    const int p  = (tid >> 2) & 15;       // spatial position in 4x4 tile
    const int cg = tid >> 6;              // cout group (8 couts each)
    const int ph = p >> 2;
    const int pw = p & 3;

    const int b    = blockIdx.z;
    const int o0   = blockIdx.y * COT;
    const int tile = blockIdx.x;
    const int h0   = (tile >> 4) * TH;
    const int w0   = (tile & 15) * TW;

    float acc[8][4];
#pragma unroll
    for (int j = 0; j < 8; ++j)
#pragma unroll
        for (int tt = 0; tt < 4; ++tt) acc[j][tt] = 0.f;

    for (int c0 = 0; c0 < CIN; c0 += CK) {
        __syncthreads();
        // --- stage x halo tile (8 ch x 6x6 x 16t), fold s[b,c] on load ---
        // 1152 float4 segments, 256 threads -> 4.5 each
        for (int li = tid; li < CK * 36 * 4; li += 256) {
            int ci  = li / 144;           // 36*4 per channel
            int rem = li - ci * 144;
            int pos = rem >> 2;
            int t4  = rem & 3;
            int pr  = pos / 6;
            int pc  = pos - pr * 6;
            int gh  = h0 - 1 + pr;
            int gw  = w0 - 1 + pc;
            float4 v = make_float4(0.f, 0.f, 0.f, 0.f);
            if (gh >= 0 && gh < H_ && gw >= 0 && gw < W_) {
                const float* xp = x +
                    ((((size_t)b * CIN + c0 + ci) * H_ + gh) * W_ + gw) * T_ + t4 * 4;
                v = *reinterpret_cast<const float4*>(xp);
            }
            float sv = g_s[b * CIN + c0 + ci];
            v.x *= sv; v.y *= sv; v.z *= sv; v.w *= sv;
            *reinterpret_cast<float4*>(&xs[ci][pos][t4 * 4]) = v;
        }
        // --- stage weights (32 cout x 8 ci x 9 taps) ---
        for (int li = tid; li < COT * CK * 9; li += 256) {
            int co  = li / 72;
            int rem = li - co * 72;
            int ci  = rem / 9;
            int tap = rem - ci * 9;
            ws[co][ci][tap] =
                weight[((size_t)(o0 + co) * CIN + c0 + ci) * 9 + tap];
        }
        __syncthreads();

        // --- compute: 8 ci x 9 taps, 32 FFMA each ---
        for (int ci = 0; ci < CK; ++ci) {
#pragma unroll
            for (int kh = 0; kh < 3; ++kh) {
#pragma unroll
                for (int kw = 0; kw < 3; ++kw) {
                    float4 xv = *reinterpret_cast<const float4*>(
                        &xs[ci][(ph + kh) * 6 + pw + kw][tg * 4]);
#pragma unroll
                    for (int j = 0; j < 8; ++j) {
                        float wv = ws[cg * 8 + j][ci][kh * 3 + kw];
                        acc[j][0] += wv * xv.x;
                        acc[j][1] += wv * xv.y;
                        acc[j][2] += wv * xv.z;
                        acc[j][3] += wv * xv.w;
                    }
                }
            }
        }
    }

    // --- epilogue: demodulate + noise + bias ---
    const int gh = h0 + ph;
    const int gw = w0 + pw;
    const float4 nz = *reinterpret_cast<const float4*>(
        noise + (((size_t)b * H_ + gh) * W_ + gw) * T_ + tg * 4);
#pragma unroll
    for (int j = 0; j < 8; ++j) {
        int o = o0 + cg * 8 + j;
        float si = g_siginv[b * COUT + o];
        float np = noise_param[o];
        float bp = bias_param[o];
        float4 r;
        r.x = acc[j][0] * si + np * nz.x + bp;
        r.y = acc[j][1] * si + np * nz.y + bp;
        r.z = acc[j][2] * si + np * nz.z + bp;
        r.w = acc[j][3] * si + np * nz.w + bp;
        float* op = out +
            ((((size_t)b * COUT + o) * H_ + gh) * W_ + gw) * T_ + tg * 4;
        *reinterpret_cast<float4*>(op) = r;
    }
}

// ---------------------------------------------------------------------------
// Launch
// inputs (metadata order): x, style, noise, weight, style_w, style_b,
//                          noise_param, bias_param
// ---------------------------------------------------------------------------
extern "C" void kernel_launch(void* const* d_in, const int* in_sizes, int n_in,
                              void* d_out, int out_size) {
    const float* x           = (const float*)d_in[0];
    const float* style       = (const float*)d_in[1];
    const float* noise       = (const float*)d_in[2];
    const float* weight      = (const float*)d_in[3];
    const float* style_w     = (const float*)d_in[4];
    const float* style_b     = (const float*)d_in[5];
    const float* noise_param = (const float*)d_in[6];
    const float* bias_param  = (const float*)d_in[7];
    float* out = (float*)d_out;

    k_style<<<B_, CIN>>>(style, style_w, style_b);
    k_sig<<<B_, COUT>>>(weight);

    dim3 grid((H_ / TH) * (W_ / TW), COUT / COT, B_);  // 256 x 4 x 4
    k_conv<<<grid, 256>>>(x, weight, noise, noise_param, bias_param, out);
}

// round 3
// speedup vs baseline: 3.5733x; 3.5733x over previous
#include <cuda_runtime.h>
#include <cuda_bf16.h>

#define B_    4
#define CIN   128
#define COUT  128
#define H_    64
#define W_    64
#define T_    16
#define SS    512

// ---- scratch (no cudaMalloc allowed) ----
__device__ float g_s[B_ * CIN];          // style scale per (b, cin)
__device__ float g_siginv[B_ * COUT];    // demodulation per (b, cout)
__device__ float g_w2[COUT * CIN];       // sum_tap w^2 per (cout, cin)
__device__ float g_wt[9 * CIN * COUT];   // [tap][ci][co], tf32-rounded

__device__ __forceinline__ float tf32r(float x) {
    unsigned u;
    asm("cvt.rna.tf32.f32 %0, %1;" : "=r"(u) : "f"(x));
    return __uint_as_float(u);
}

// ---------------------------------------------------------------------------
// Prologue: transpose weights to [tap][ci][co] (tf32-rounded) + per-(o,i) w^2
// grid = 128 (ci), block = 128 (co)
// ---------------------------------------------------------------------------
__global__ void k_wprep(const float* __restrict__ weight) {
    int i = blockIdx.x;
    int o = threadIdx.x;
    const float* wp = weight + (size_t)o * CIN * 9 + i * 9;
    float wsq = 0.f;
#pragma unroll
    for (int tap = 0; tap < 9; ++tap) {
        float w = wp[tap];
        wsq += w * w;
        g_wt[((size_t)tap * CIN + i) * COUT + o] = tf32r(w);
    }
    g_w2[o * CIN + i] = wsq;
}

// ---------------------------------------------------------------------------
// s[b,i] = style[b,:].style_w[i,:] + style_b[i]  — one warp per dot
// grid = 64, block = 256 (512 warps total)
// ---------------------------------------------------------------------------
__global__ void k_style(const float* __restrict__ style,
                        const float* __restrict__ style_w,
                        const float* __restrict__ style_b) {
    int wg   = blockIdx.x * 8 + (threadIdx.x >> 5);
    int lane = threadIdx.x & 31;
    int b = wg >> 7;
    int i = wg & 127;
    const float* st = style + (size_t)b * SS;
    const float* sw = style_w + (size_t)i * SS;
    float acc = 0.f;
#pragma unroll
    for (int r = 0; r < 16; ++r) acc += st[lane + 32 * r] * sw[lane + 32 * r];
#pragma unroll
    for (int off = 16; off; off >>= 1) acc += __shfl_xor_sync(~0u, acc, off);
    if (lane == 0) g_s[b * CIN + i] = acc + style_b[i];
}

// ---------------------------------------------------------------------------
// sig_inv[b,o] = rsqrt( sum_i g_w2[o,i] * s[b,i]^2 + 1e-8 )  — warp per (b,o)
// ---------------------------------------------------------------------------
__global__ void k_sig2() {
    int wg   = blockIdx.x * 8 + (threadIdx.x >> 5);
    int lane = threadIdx.x & 31;
    int b = wg >> 7;
    int o = wg & 127;
    float acc = 0.f;
#pragma unroll
    for (int r = 0; r < 4; ++r) {
        int i = lane + 32 * r;
        float s = g_s[b * CIN + i];
        acc += g_w2[o * CIN + i] * s * s;
    }
#pragma unroll
    for (int off = 16; off; off >>= 1) acc += __shfl_xor_sync(~0u, acc, off);
    if (lane == 0) g_siginv[b * COUT + o] = rsqrtf(acc + 1e-8f);
}

// ---------------------------------------------------------------------------
// Main conv as implicit GEMM on tensor cores (tf32 mma.sync m16n8k8).
// CTA tile: M=128 (all couts) x N=128 (8 w x 16 t at fixed b,h). K = 9*128.
// 8 warps = 4M x 2N, warp tile 32x64. cin chunk = 8 per stage.
// ---------------------------------------------------------------------------
#define SA_STRIDE 136    // 128 co + 8 pad  -> conflict-free A frags
#define SX_STRIDE 488    // 480 (3h*10w*16t) + 8 pad -> conflict-free B frags
#define SA_FLOATS (72 * SA_STRIDE)   // 9 taps * 8 ci rows
#define SX_FLOATS (8 * SX_STRIDE)
#define SMEM_BYTES ((SA_FLOATS + SX_FLOATS) * 4)

__global__ void __launch_bounds__(256, 2)
k_conv(const float* __restrict__ x,
       const float* __restrict__ noise,
       const float* __restrict__ noise_param,
       const float* __restrict__ bias_param,
       float* __restrict__ out) {
    extern __shared__ float smem[];
    float* sA = smem;               // [72][136] : row = tap*8 + ci
    float* sX = smem + SA_FLOATS;   // [8][488]  : [ci][3h][10w][16t]

    const int tid  = threadIdx.x;
    const int lane = tid & 31;
    const int wid  = tid >> 5;
    const int g    = lane >> 2;     // group id (0..7)
    const int q    = lane & 3;      // thread-in-group (0..3)
    const int mwarp = (wid >> 1) * 32;
    const int nwarp = (wid & 1) * 64;

    const int bid = blockIdx.x;
    const int b   = bid >> 9;
    const int h   = (bid >> 3) & 63;
    const int w0  = (bid & 7) * 8;

    float acc[2][8][4];
#pragma unroll
    for (int mf = 0; mf < 2; ++mf)
#pragma unroll
        for (int nf = 0; nf < 8; ++nf)
#pragma unroll
            for (int r = 0; r < 4; ++r) acc[mf][nf][r] = 0.f;

#pragma unroll 1
    for (int c0 = 0; c0 < CIN; c0 += 8) {
        __syncthreads();
        // ---- stage halo: 8 ci x 3h x 10w x 16t, fold s, round to tf32 ----
        for (int li = tid; li < 960; li += 256) {
            int ci  = li / 120;
            int r   = li - ci * 120;
            int pos = r >> 2;            // 0..29 : dh*10 + wl
            int t4  = (r & 3) * 4;
            int dh  = pos / 10;
            int wl  = pos - dh * 10;
            int gh  = h + dh - 1;
            int gw  = w0 + wl - 1;
            float4 v = make_float4(0.f, 0.f, 0.f, 0.f);
            if ((unsigned)gh < (unsigned)H_ && (unsigned)gw < (unsigned)W_) {
                v = *reinterpret_cast<const float4*>(
                    x + ((((size_t)b * CIN + c0 + ci) * H_ + gh) * W_ + gw) * T_ + t4);
            }
            float sv = g_s[b * CIN + c0 + ci];
            v.x = tf32r(v.x * sv);
            v.y = tf32r(v.y * sv);
            v.z = tf32r(v.z * sv);
            v.w = tf32r(v.w * sv);
            *reinterpret_cast<float4*>(sX + ci * SX_STRIDE + pos * 16 + t4) = v;
        }
        // ---- stage weights: 9 taps x 8 ci x 128 co (pre-transposed, tf32) ----
        for (int li = tid; li < 2304; li += 256) {
            int row = li >> 5;            // tap*8 + k
            int c4  = (li & 31) * 4;
            int tap = row >> 3;
            int k   = row & 7;
            float4 v = *reinterpret_cast<const float4*>(
                g_wt + ((size_t)tap * CIN + c0 + k) * COUT + c4);
            *reinterpret_cast<float4*>(sA + row * SA_STRIDE + c4) = v;
        }
        __syncthreads();

        // ---- compute: 9 taps, K=8 each ----
#pragma unroll
        for (int kh = 0; kh < 3; ++kh) {
#pragma unroll
            for (int kw = 0; kw < 3; ++kw) {
                const int t8 = (kh * 3 + kw) * 8;
                const int tb = (kh * 10 + kw) * 16;

                unsigned a[2][4];
#pragma unroll
                for (int mf = 0; mf < 2; ++mf) {
                    const float* ap = sA + (t8 + q) * SA_STRIDE + mwarp + mf * 16 + g;
                    a[mf][0] = __float_as_uint(ap[0]);
                    a[mf][1] = __float_as_uint(ap[8]);
                    a[mf][2] = __float_as_uint(ap[4 * SA_STRIDE]);
                    a[mf][3] = __float_as_uint(ap[4 * SA_STRIDE + 8]);
                }
                unsigned b0[8], b1[8];
                const float* bp = sX + q * SX_STRIDE + tb + nwarp + g;
#pragma unroll
                for (int nf = 0; nf < 8; ++nf) {
                    b0[nf] = __float_as_uint(bp[nf * 8]);
                    b1[nf] = __float_as_uint(bp[nf * 8 + 4 * SX_STRIDE]);
                }
#pragma unroll
                for (int mf = 0; mf < 2; ++mf) {
#pragma unroll
                    for (int nf = 0; nf < 8; ++nf) {
                        asm volatile(
                            "mma.sync.aligned.m16n8k8.row.col.f32.tf32.tf32.f32 "
                            "{%0,%1,%2,%3}, {%4,%5,%6,%7}, {%8,%9}, {%0,%1,%2,%3};"
                            : "+f"(acc[mf][nf][0]), "+f"(acc[mf][nf][1]),
                              "+f"(acc[mf][nf][2]), "+f"(acc[mf][nf][3])
                            : "r"(a[mf][0]), "r"(a[mf][1]), "r"(a[mf][2]), "r"(a[mf][3]),
                              "r"(b0[nf]), "r"(b1[nf]));
                    }
                }
            }
        }
    }

    // ---- epilogue: demodulate + noise + bias ----
    float si[2][2], np[2][2], bp2[2][2];
#pragma unroll
    for (int mf = 0; mf < 2; ++mf)
#pragma unroll
        for (int hf = 0; hf < 2; ++hf) {
            int m = mwarp + mf * 16 + g + hf * 8;
            si[mf][hf]  = g_siginv[b * COUT + m];
            np[mf][hf]  = noise_param[m];
            bp2[mf][hf] = bias_param[m];
        }
#pragma unroll
    for (int nf = 0; nf < 8; ++nf) {
        int n  = nwarp + nf * 8 + q * 2;
        int wl = n >> 4;
        int t  = n & 15;
        float2 nz = *reinterpret_cast<const float2*>(
            noise + (((size_t)b * H_ + h) * W_ + w0 + wl) * T_ + t);
#pragma unroll
        for (int mf = 0; mf < 2; ++mf) {
#pragma unroll
            for (int hf = 0; hf < 2; ++hf) {
                int m = mwarp + mf * 16 + g + hf * 8;
                float2 r;
                r.x = acc[mf][nf][hf * 2 + 0] * si[mf][hf] + np[mf][hf] * nz.x + bp2[mf][hf];
                r.y = acc[mf][nf][hf * 2 + 1] * si[mf][hf] + np[mf][hf] * nz.y + bp2[mf][hf];
                *reinterpret_cast<float2*>(
                    out + ((((size_t)b * COUT + m) * H_ + h) * W_ + w0 + wl) * T_ + t) = r;
            }
        }
    }
}

// ---------------------------------------------------------------------------
// Launch. inputs: x, style, noise, weight, style_w, style_b, noise_param,
//                 bias_param
// ---------------------------------------------------------------------------
extern "C" void kernel_launch(void* const* d_in, const int* in_sizes, int n_in,
                              void* d_out, int out_size) {
    const float* x           = (const float*)d_in[0];
    const float* style       = (const float*)d_in[1];
    const float* noise       = (const float*)d_in[2];
    const float* weight      = (const float*)d_in[3];
    const float* style_w     = (const float*)d_in[4];
    const float* style_b     = (const float*)d_in[5];
    const float* noise_param = (const float*)d_in[6];
    const float* bias_param  = (const float*)d_in[7];
    float* out = (float*)d_out;

    k_wprep<<<CIN, COUT>>>(weight);
    k_style<<<64, 256>>>(style, style_w, style_b);
    k_sig2<<<64, 256>>>();

    cudaFuncSetAttribute(k_conv, cudaFuncAttributeMaxDynamicSharedMemorySize,
                         SMEM_BYTES);
    k_conv<<<2048, 256, SMEM_BYTES>>>(x, noise, noise_param, bias_param, out);
}

// round 6
// speedup vs baseline: 4.5210x; 1.2652x over previous
#include <cuda_runtime.h>
#include <cstdint>

#define B_    4
#define CIN   128
#define COUT  128
#define H_    64
#define W_    64
#define T_    16
#define SS    512
#define NPOS  (H_ * W_ * T_)

// ---- static device scratch (no cudaMalloc allowed) ----
__device__ float g_s[B_ * CIN];
__device__ float g_w2[COUT * CIN];
__device__ float g_siginv[B_ * COUT];
__device__ float g_wt2[(size_t)B_ * 9 * CIN * COUT];  // [b][tap][ci][cout], tf32(w*s)
__device__ float g_xs[(size_t)B_ * CIN * NPOS];       // tf32-rounded x

__device__ __forceinline__ float tf32r(float x) {
    unsigned u;
    asm("cvt.rna.tf32.f32 %0, %1;" : "=r"(u) : "f"(x));
    return __uint_as_float(u);
}

__device__ __forceinline__ uint32_t smem_u32(const void* p) {
    uint32_t a;
    asm("{ .reg .u64 t; cvta.to.shared.u64 t, %1; cvt.u32.u64 %0, t; }" : "=r"(a) : "l"(p));
    return a;
}

__device__ __forceinline__ void cp16(uint32_t dst, const float* src, int ok) {
    asm volatile("cp.async.cg.shared.global [%0], [%1], 16, %2;"
                 :: "r"(dst), "l"(src), "r"(ok ? 16 : 0) : "memory");
}

// ---------------------------------------------------------------------------
// Prologue kernels
// ---------------------------------------------------------------------------
__global__ void k_style(const float* __restrict__ style,
                        const float* __restrict__ style_w,
                        const float* __restrict__ style_b) {
    int wg = blockIdx.x * 8 + (threadIdx.x >> 5);
    int lane = threadIdx.x & 31;
    int b = wg >> 7, i = wg & 127;
    const float* st = style + (size_t)b * SS;
    const float* sw = style_w + (size_t)i * SS;
    float acc = 0.f;
#pragma unroll
    for (int r = 0; r < 16; ++r) acc += st[lane + 32 * r] * sw[lane + 32 * r];
#pragma unroll
    for (int o = 16; o; o >>= 1) acc += __shfl_xor_sync(~0u, acc, o);
    if (lane == 0) g_s[b * CIN + i] = acc + style_b[i];
}

// g_wt2[b][tap][ci][cout] = tf32(w[cout][ci][tap] * s[b][ci]); g_w2 once
__global__ void k_wmod(const float* __restrict__ weight) {
    int ci = blockIdx.x, b = blockIdx.y, o = threadIdx.x;
    float s = g_s[b * CIN + ci];
    float wsq = 0.f;
#pragma unroll
    for (int tap = 0; tap < 9; ++tap) {
        float w = weight[((size_t)o * CIN + ci) * 9 + tap];
        wsq += w * w;
        g_wt2[(((size_t)b * 9 + tap) * CIN + ci) * COUT + o] = tf32r(w * s);
    }
    if (b == 0) g_w2[o * CIN + ci] = wsq;
}

__global__ void k_sig2() {
    int wg = blockIdx.x * 8 + (threadIdx.x >> 5);
    int lane = threadIdx.x & 31;
    int b = wg >> 7, o = wg & 127;
    float acc = 0.f;
#pragma unroll
    for (int r = 0; r < 4; ++r) {
        int i = lane + 32 * r;
        float s = g_s[b * CIN + i];
        acc += g_w2[o * CIN + i] * s * s;
    }
#pragma unroll
    for (int off = 16; off; off >>= 1) acc += __shfl_xor_sync(~0u, acc, off);
    if (lane == 0) g_siginv[b * COUT + o] = rsqrtf(acc + 1e-8f);
}

// g_xs = tf32(x), vectorized. 33.55M floats / 4 per thread = 8.39M threads.
__global__ void k_xcvt(const float* __restrict__ x) {
    size_t i = ((size_t)blockIdx.x * blockDim.x + threadIdx.x) * 4;
    float4 v = *reinterpret_cast<const float4*>(x + i);
    v.x = tf32r(v.x); v.y = tf32r(v.y); v.z = tf32r(v.z); v.w = tf32r(v.w);
    *reinterpret_cast<float4*>(g_xs + i) = v;
}

// ---------------------------------------------------------------------------
// Main conv: implicit GEMM, tf32 mma.sync m16n8k8, cp.async double-buffered.
// CTA 128 thr = 4 warps (2M x 2N), warp tile 64x64. CTA tile M=128 x N=128
// (8 w x 16 t at fixed b,h). 16 ci-chunks of 8.
// ---------------------------------------------------------------------------
#define SA_STRIDE 136
#define SX_STRIDE 488
#define SA_FLOATS (72 * SA_STRIDE)           // 9792
#define SX_FLOATS (8 * SX_STRIDE)            // 3904
#define STAGE_FLOATS (SA_FLOATS + SX_FLOATS) // 13696
#define SMEM_BYTES (2 * STAGE_FLOATS * 4)    // 109568

__global__ void __launch_bounds__(128)
k_conv(const float* __restrict__ noise,
       const float* __restrict__ noise_param,
       const float* __restrict__ bias_param,
       float* __restrict__ out) {
    extern __shared__ float smem[];
    const uint32_t sb = smem_u32(smem);

    const int tid  = threadIdx.x;
    const int lane = tid & 31;
    const int wid  = tid >> 5;
    const int g    = lane >> 2;
    const int q    = lane & 3;
    const int mwarp = (wid >> 1) * 64;
    const int nwarp = (wid & 1) * 64;

    const int bid = blockIdx.x;
    const int b  = bid >> 9;
    const int h  = (bid >> 3) & 63;
    const int w0 = (bid & 7) * 8;

    float acc[4][8][4];
#pragma unroll
    for (int mf = 0; mf < 4; ++mf)
#pragma unroll
        for (int nf = 0; nf < 8; ++nf)
#pragma unroll
            for (int r = 0; r < 4; ++r) acc[mf][nf][r] = 0.f;

    // ---- async stage of chunk c (8 ci) into stage buffer s ----
    auto stage_load = [&](int c, int s) {
        const int c0 = c * 8;
        const uint32_t sa = sb + (uint32_t)(s * STAGE_FLOATS) * 4;
        const uint32_t sx = sa + SA_FLOATS * 4;
        // A: 72 rows (tap*8+k) x 128 couts = 2304 x 16B
#pragma unroll
        for (int i = 0; i < 18; ++i) {
            int li  = tid + i * 128;
            int row = li >> 5;
            int seg = li & 31;
            int tap = row >> 3, k = row & 7;
            const float* src = g_wt2 +
                (((size_t)(b * 9 + tap) * CIN) + c0 + k) * COUT + seg * 4;
            cp16(sa + (uint32_t)(row * SA_STRIDE + seg * 4) * 4, src, 1);
        }
        // X: 8 ci x 30 pos x 4 segs = 960 x 16B (zfill OOB)
        for (int li = tid; li < 960; li += 128) {
            int ci  = li / 120;
            int r   = li - ci * 120;
            int pos = r >> 2;
            int t4  = (r & 3) << 2;
            int dh  = pos / 10;
            int wl  = pos - dh * 10;
            int gh  = h + dh - 1;
            int gw  = w0 + wl - 1;
            int ok  = ((unsigned)gh < (unsigned)H_) & ((unsigned)gw < (unsigned)W_);
            int ghc = ok ? gh : 0;
            int gwc = ok ? gw : 0;
            const float* src = g_xs +
                ((((size_t)b * CIN + c0 + ci) * H_ + ghc) * W_ + gwc) * T_ + t4;
            cp16(sx + (uint32_t)(ci * SX_STRIDE + pos * 16 + t4) * 4, src, ok);
        }
    };

    auto compute = [&](int s) {
        const float* sA = smem + s * STAGE_FLOATS;
        const float* sX = sA + SA_FLOATS;
#pragma unroll
        for (int kh = 0; kh < 3; ++kh) {
            // 12 shared B-frag pairs cover all 3 kw shifts
            unsigned b0[12], b1[12];
            const float* bp = sX + q * SX_STRIDE + kh * 160 + nwarp + g;
#pragma unroll
            for (int f = 0; f < 12; ++f) {
                b0[f] = __float_as_uint(bp[f * 8]);
                b1[f] = __float_as_uint(bp[f * 8 + 4 * SX_STRIDE]);
            }
#pragma unroll
            for (int kw = 0; kw < 3; ++kw) {
                const int t8 = (kh * 3 + kw) * 8;
                unsigned a[4][4];
                const float* ap = sA + (t8 + q) * SA_STRIDE + mwarp + g;
#pragma unroll
                for (int mf = 0; mf < 4; ++mf) {
                    const float* p = ap + mf * 16;
                    a[mf][0] = __float_as_uint(p[0]);
                    a[mf][1] = __float_as_uint(p[8]);
                    a[mf][2] = __float_as_uint(p[4 * SA_STRIDE]);
                    a[mf][3] = __float_as_uint(p[4 * SA_STRIDE + 8]);
                }
#pragma unroll
                for (int mf = 0; mf < 4; ++mf) {
#pragma unroll
                    for (int nf = 0; nf < 8; ++nf) {
                        const int f = kw * 2 + nf;
                        asm volatile(
                            "mma.sync.aligned.m16n8k8.row.col.f32.tf32.tf32.f32 "
                            "{%0,%1,%2,%3}, {%4,%5,%6,%7}, {%8,%9}, {%0,%1,%2,%3};"
                            : "+f"(acc[mf][nf][0]), "+f"(acc[mf][nf][1]),
                              "+f"(acc[mf][nf][2]), "+f"(acc[mf][nf][3])
                            : "r"(a[mf][0]), "r"(a[mf][1]), "r"(a[mf][2]), "r"(a[mf][3]),
                              "r"(b0[f]), "r"(b1[f]));
                    }
                }
            }
        }
    };

    // ---- pipelined mainloop ----
    stage_load(0, 0);
    asm volatile("cp.async.commit_group;" ::: "memory");
#pragma unroll 1
    for (int c = 0; c < 16; ++c) {
        if (c < 15) {
            stage_load(c + 1, (c + 1) & 1);
            asm volatile("cp.async.commit_group;" ::: "memory");
            asm volatile("cp.async.wait_group 1;" ::: "memory");
        } else {
            asm volatile("cp.async.wait_group 0;" ::: "memory");
        }
        __syncthreads();
        compute(c & 1);
        __syncthreads();
    }

    // ---- epilogue: demodulate + noise + bias ----
    float si[4][2], np[4][2], bp2[4][2];
#pragma unroll
    for (int mf = 0; mf < 4; ++mf)
#pragma unroll
        for (int hf = 0; hf < 2; ++hf) {
            int m = mwarp + mf * 16 + g + hf * 8;
            si[mf][hf]  = g_siginv[b * COUT + m];
            np[mf][hf]  = noise_param[m];
            bp2[mf][hf] = bias_param[m];
        }
#pragma unroll
    for (int nf = 0; nf < 8; ++nf) {
        int n  = nwarp + nf * 8 + q * 2;
        int wl = n >> 4;
        int t  = n & 15;
        float2 nz = *reinterpret_cast<const float2*>(
            noise + (((size_t)b * H_ + h) * W_ + w0 + wl) * T_ + t);
#pragma unroll
        for (int mf = 0; mf < 4; ++mf) {
#pragma unroll
            for (int hf = 0; hf < 2; ++hf) {
                int m = mwarp + mf * 16 + g + hf * 8;
                float2 r;
                r.x = acc[mf][nf][hf * 2 + 0] * si[mf][hf] + np[mf][hf] * nz.x + bp2[mf][hf];
                r.y = acc[mf][nf][hf * 2 + 1] * si[mf][hf] + np[mf][hf] * nz.y + bp2[mf][hf];
                *reinterpret_cast<float2*>(
                    out + ((((size_t)b * COUT + m) * H_ + h) * W_ + w0 + wl) * T_ + t) = r;
            }
        }
    }
}

// ---------------------------------------------------------------------------
// Launch. inputs: x, style, noise, weight, style_w, style_b, noise_param,
//                 bias_param
// ---------------------------------------------------------------------------
extern "C" void kernel_launch(void* const* d_in, const int* in_sizes, int n_in,
                              void* d_out, int out_size) {
    const float* x           = (const float*)d_in[0];
    const float* style       = (const float*)d_in[1];
    const float* noise       = (const float*)d_in[2];
    const float* weight      = (const float*)d_in[3];
    const float* style_w     = (const float*)d_in[4];
    const float* style_b     = (const float*)d_in[5];
    const float* noise_param = (const float*)d_in[6];
    const float* bias_param  = (const float*)d_in[7];
    float* out = (float*)d_out;

    k_style<<<64, 256>>>(style, style_w, style_b);
    k_wmod<<<dim3(CIN, B_), COUT>>>(weight);
    k_sig2<<<64, 256>>>();
    // 33.55M floats = 8.39M float4 -> 32768 blocks x 256 threads, 1 each
    k_xcvt<<<32768, 256>>>(x);

    cudaFuncSetAttribute(k_conv, cudaFuncAttributeMaxDynamicSharedMemorySize,
                         SMEM_BYTES);
    k_conv<<<2048, 128, SMEM_BYTES>>>(noise, noise_param, bias_param, out);
}